// round 15
// baseline (speedup 1.0000x reference)
#include <cuda_runtime.h>
#include <cstdint>

// ---------------- problem constants ----------------
#define NB 4
#define NC 512
#define NG 2048
#define CH 3
#define OC 64
#define NBAS 10
#define NPT 8192
#define NBIN 64
#define EPSV 1e-6f
#define BN_EPS 1e-5f

// output layout (float32, concatenated in return order)
#define OFF_Y   0
#define OFF_NF  524288
#define OFF_FP  598016
#define OFF_NH1 671744
#define OFF_H0  745472

// scratch (device globals)
__device__ float g_pos[9 * NPT];          // SoA [chan][b*NG+g]
__device__ float g_conv[9 * NPT];
__device__ float2 g_sxy[NB * 3 * NC];     // bucketed (x,y) per (b,coord)
__device__ int   g_bstart[NB * 3 * (NBIN + 1)];
__device__ float g_binfo[NB * 3 * 2];     // min, scale per (b,coord)
__device__ unsigned long long g_isum[9];
__device__ unsigned long long g_isq[9];

#define S_SUM 1.7179869184e10   // 2^34
#define S_SQ  2.68435456e8      // 2^28

__device__ __forceinline__ float ex2f(float x) {
    float y;
    asm("ex2.approx.ftz.f32 %0, %1;" : "=f"(y) : "f"(x));
    return y;
}

// ============================================================
// Kernel 0: deterministic 64-bin bucket multisplit per (b,coord).
//           (unchanged -- proven R10/R12)
// ============================================================
__global__ void __launch_bounds__(NC)
k0_bucket(const float* __restrict__ xc, const float* __restrict__ yc)
{
    __shared__ float sx[NC], sy[NC];
    __shared__ int scnt[16 * NBIN];      // [warp][bin]
    __shared__ int stotal[NBIN];
    __shared__ int sbstart[NBIN + 1];
    __shared__ float wmn[16], wmx[16];
    __shared__ float sminv, sscale;

    const int bc = blockIdx.x;           // 0..11
    const int b = bc / 3, c = bc - b * 3;
    const int t = threadIdx.x;
    const int w = t >> 5, lane = t & 31;

    if (bc == 0 && t < 9) { g_isum[t] = 0ull; g_isq[t] = 0ull; }

    float x = xc[(b * NC + t) * 3 + c];
    float y = yc[(b * NC + t) * 3 + c];

    scnt[t] = 0;
    scnt[NC + t] = 0;

    float mn = x, mx = x;
#pragma unroll
    for (int off = 16; off > 0; off >>= 1) {
        mn = fminf(mn, __shfl_xor_sync(0xffffffffu, mn, off));
        mx = fmaxf(mx, __shfl_xor_sync(0xffffffffu, mx, off));
    }
    if (lane == 0) { wmn[w] = mn; wmx[w] = mx; }
    __syncthreads();
    if (t == 0) {
        float m = wmn[0], M = wmx[0];
#pragma unroll
        for (int i = 1; i < 16; i++) { m = fminf(m, wmn[i]); M = fmaxf(M, wmx[i]); }
        sminv = m;
        sscale = (M > m) ? 63.9999f / (M - m) : 0.0f;
    }
    __syncthreads();

    const float mnv = sminv, sc = sscale;
    int bin = (int)((x - mnv) * sc);
    bin = min(max(bin, 0), NBIN - 1);

    unsigned msk = __match_any_sync(0xffffffffu, bin);
    int rank = __popc(msk & ((1u << lane) - 1u));
    if (rank == 0) scnt[w * NBIN + bin] = __popc(msk);
    __syncthreads();

    if (t < NBIN) {
        int run = 0;
#pragma unroll
        for (int w2 = 0; w2 < 16; w2++) {
            int v = scnt[w2 * NBIN + t];
            scnt[w2 * NBIN + t] = run;
            run += v;
        }
        stotal[t] = run;
    }
    __syncthreads();

    for (int off = 1; off < NBIN; off <<= 1) {
        int v = 0;
        if (t < NBIN && t >= off) v = stotal[t - off];
        __syncthreads();
        if (t < NBIN && t >= off) stotal[t] += v;
        __syncthreads();
    }
    if (t < NBIN) sbstart[t + 1] = stotal[t];
    if (t == 0) sbstart[0] = 0;
    __syncthreads();

    int pos = sbstart[bin] + scnt[w * NBIN + bin] + rank;
    sx[pos] = x;
    sy[pos] = y;
    __syncthreads();

    g_sxy[bc * NC + t] = make_float2(sx[t], sy[t]);
    if (t < NBIN + 1) g_bstart[bc * (NBIN + 1) + t] = sbstart[t];
    if (t == 0) { g_binfo[bc * 2] = mnv; g_binfo[bc * 2 + 1] = sc; }
}

// ============================================================
// Kernel 1: windowed RBF sums + fourier prior.
//           R = 7.0*sigma_max (annulus weight <= 2.3e-11),
//           2 points per warp (halved staging), R14 epilogue.
// ============================================================
__global__ void __launch_bounds__(256)
k1_rbf(const float* __restrict__ xg, const float* __restrict__ sigma,
       const float* __restrict__ mu, const float* __restrict__ eps1,
       const float* __restrict__ bu, const float* __restrict__ rw,
       float* __restrict__ out)
{
    __shared__ float2 sxy[3 * NC];
    __shared__ int sbs[3 * (NBIN + 1)];
    __shared__ float sminf[3], sscalef[3];
    __shared__ float ssw[NBAS * 3], ssb[NBAS * 3];
    __shared__ float scoef[3];
    __shared__ float sRmax;
    __shared__ int   sktab[12];          // fourier k-index table [grp*4+i]
    __shared__ float swgt[12];           // fourier weights (0 = dummy pad)
    __shared__ float sred[8][144];       // per-warp reduce scratch [r<8][18]

    const int b = blockIdx.y;
    const int tid = threadIdx.x;

    for (int idx = tid; idx < 3 * NC; idx += 256)
        sxy[idx] = g_sxy[b * 3 * NC + idx];
    for (int idx = tid; idx < 3 * (NBIN + 1); idx += 256)
        sbs[idx] = g_bstart[b * 3 * (NBIN + 1) + idx];
    if (tid < 3) {
        sminf[tid]   = g_binfo[(b * 3 + tid) * 2];
        sscalef[tid] = g_binfo[(b * 3 + tid) * 2 + 1];
    }
    if (tid >= 128 && tid < 128 + NBAS * 3) {
        int q = tid - 128;
        int k = q / 3, p = q - k * 3;
        float w_std = 1.0f / (expf(sigma[p]) + EPSV);
        ssw[q] = expf(mu[p]) + w_std * eps1[(b * NBAS + k) * 3 + p];
        ssb[q] = 6.283185307179586f * bu[(b * NBAS + k) * 3 + p];
    }
    if (tid >= 176 && tid < 179) {
        int p = tid - 176;
        float s = expf(sigma[p]) + EPSV;
        float inv = 1.0f / s;
        scoef[p] = -0.5f * inv * inv * 1.4426950408889634f;
    }
    if (tid == 192) {
        float s0 = expf(sigma[0]) + EPSV;
        float s1 = expf(sigma[1]) + EPSV;
        float s2 = expf(sigma[2]) + EPSV;
        sRmax = 7.0f * fmaxf(s0, fmaxf(s1, s2));
    }
    if (tid >= 200 && tid < 212) {
        int e = tid - 200;
        int grp = e >> 2, i = e & 3;
        int kk; float wv;
        if (grp == 0)      { kk = i;                       wv = rw[i]; }
        else if (grp == 1) { kk = (i < 3) ? 4 + i : 0;     wv = (i < 3) ? rw[4 + i] : 0.f; }
        else               { kk = (i < 3) ? 7 + i : 0;     wv = (i < 3) ? rw[7 + i] : 0.f; }
        sktab[e] = kk;
        swgt[e] = wv;
    }
    __syncthreads();

    const int wid = tid >> 5, lane = tid & 31;
    const float c0 = scoef[0], c1 = scoef[1], c2 = scoef[2];
    const float R = sRmax;

#pragma unroll
    for (int sub = 0; sub < 2; sub++) {
        const int g = blockIdx.x * 16 + wid * 2 + sub;
        const float* xgp = &xg[(b * NG + g) * 3];
        const float xg0 = xgp[0], xg1 = xgp[1], xg2 = xgp[2];

        float h0[9], h1[9];
        {
            const float xgv3[3] = { xg0, xg1, xg2 };
#pragma unroll
            for (int c = 0; c < 3; c++) {
                const float xgc = xgv3[c];
                const float2* sp = sxy + c * NC;
                const int* bsc = sbs + c * (NBIN + 1);
                const float mnc = sminf[c], scc = sscalef[c];

                int il = (int)floorf((xgc - R - mnc) * scc);
                int ih = (int)floorf((xgc + R - mnc) * scc);
                il = min(max(il, 0), NBIN - 1);
                ih = min(max(ih, 0), NBIN - 1);
                const int lo = bsc[il], hi = bsc[ih + 1];

                float a0 = 0.f, a1 = 0.f, a2 = 0.f;
                float b0 = 0.f, b1 = 0.f, b2 = 0.f;
                for (int n = lo + lane; n < hi; n += 32) {
                    float2 v = sp[n];
                    float d = v.x - xgc;
                    float s = d * d;
                    float e;
                    e = ex2f(s * c0); a0 += e; b0 = fmaf(e, v.y, b0);
                    e = ex2f(s * c1); a1 += e; b1 = fmaf(e, v.y, b1);
                    e = ex2f(s * c2); a2 += e; b2 = fmaf(e, v.y, b2);
                }
                h0[c * 3 + 0] = a0; h1[c * 3 + 0] = b0;
                h0[c * 3 + 1] = a1; h1[c * 3 + 1] = b1;
                h0[c * 3 + 2] = a2; h1[c * 3 + 2] = b2;
            }
        }

        // partial butterfly: offsets 16, 8 -> mod-8 partials
#pragma unroll
        for (int off = 16; off >= 8; off >>= 1) {
#pragma unroll
            for (int j = 0; j < 9; j++) {
                h0[j] += __shfl_xor_sync(0xffffffffu, h0[j], off);
                h1[j] += __shfl_xor_sync(0xffffffffu, h1[j], off);
            }
        }
        __syncwarp();                       // prior sred reads done (sub=1)
        if (lane < 8) {
#pragma unroll
            for (int j = 0; j < 9; j++) {
                sred[wid][lane * 18 + j]     = h0[j];
                sred[wid][lane * 18 + 9 + j] = h1[j];
            }
        }
        __syncwarp();
        float hsum = 0.f;
        {
            int le = (lane < 18) ? lane : 0;
#pragma unroll
            for (int r = 0; r < 8; r++)
                hsum += sred[wid][r * 18 + le];
        }
        float h1v = __shfl_sync(0xffffffffu, hsum, lane + 9);   // valid lane<9

        // fourier: 27 lanes, 4 uniform cos each
        float fpart = 0.f;
        {
            int le = (lane < 27) ? lane : 26;
            int grp = le / 9;
            int j = le - grp * 9;
            int c = j / 3, p = j - c * 3;
            float xgc = (c == 0) ? xg0 : ((c == 1) ? xg1 : xg2);
#pragma unroll
            for (int i = 0; i < 4; i++) {
                int e = grp * 4 + i;
                int kk = sktab[e];
                float arg = __fadd_rn(__fmul_rn(ssw[kk * 3 + p], xgc), ssb[kk * 3 + p]);
                fpart = fmaf(swgt[e], cosf(arg), fpart);
            }
        }
        float fpB = __shfl_sync(0xffffffffu, fpart, lane + 9);
        float fpC = __shfl_sync(0xffffffffu, fpart, lane + 18);

        if (lane < 9) {
            float h0v = hsum;
            float nh1 = h1v / (h0v + EPSV);
            float fp = ((fpart + fpB) + fpC) * 0.4472135954999579f;

            int pt = b * NG + g;
            int base = pt * 9 + lane;
            out[OFF_H0 + base] = h0v;
            out[OFF_NH1 + base] = nh1;
            out[OFF_FP + base] = fp;
            g_pos[lane * NPT + pt] = nh1 + fp;
        }
    }
}

// ============================================================
// Kernel 2: depthwise convs + deterministic BN partial sums.
//           Reduction via fp64 warp shuffles (1 syncthreads).
// ============================================================
__global__ void __launch_bounds__(512)
k2_conv(const float* __restrict__ w1, const float* __restrict__ b1,
        const float* __restrict__ w2, const float* __restrict__ b2,
        const float* __restrict__ w3, const float* __restrict__ b3)
{
    __shared__ double swp[16], swq[16];
    const int tid = threadIdx.x;
    const int wid = tid >> 5, lane = tid & 31;
    const int t = blockIdx.x * 512 + tid;
    const int chan = blockIdx.x >> 4;
    const int rem = t - chan * NPT;
    const int g = rem & (NG - 1);
    const int c = chan / 3, p = chan - c * 3;

    const int ksz = (p == 0) ? 3 : ((p == 1) ? 5 : 9);
    const int pad = ksz >> 1;
    const float* w  = (p == 0) ? w1 : ((p == 1) ? w2 : w3);
    const float* bb = (p == 0) ? b1 : ((p == 1) ? b2 : b3);

    float acc = bb[c];
    const float* src = &g_pos[t - g];
    for (int tt = 0; tt < ksz; tt++) {
        int gg = g + tt - pad;
        if (gg >= 0 && gg < NG)
            acc = fmaf(src[gg], w[c * ksz + tt], acc);
    }
    g_conv[t] = acc;

    double v = (double)acc;
    double vq = v * v;
#pragma unroll
    for (int off = 16; off > 0; off >>= 1) {
        v  += __shfl_down_sync(0xffffffffu, v, off);
        vq += __shfl_down_sync(0xffffffffu, vq, off);
    }
    if (lane == 0) { swp[wid] = v; swq[wid] = vq; }
    __syncthreads();
    if (wid == 0) {
        double s = (lane < 16) ? swp[lane] : 0.0;
        double q = (lane < 16) ? swq[lane] : 0.0;
#pragma unroll
        for (int off = 8; off > 0; off >>= 1) {
            s += __shfl_down_sync(0xffffffffu, s, off);
            q += __shfl_down_sync(0xffffffffu, q, off);
        }
        if (lane == 0) {
            long long is = __double2ll_rn(s * S_SUM);
            long long iq = __double2ll_rn(q * S_SQ);
            atomicAdd(&g_isum[chan], (unsigned long long)is);
            atomicAdd(&g_isq[chan],  (unsigned long long)iq);
        }
    }
}

// ============================================================
// Kernel 3: warp-per-point barrier-free head (unchanged R13).
// ============================================================
__global__ void __launch_bounds__(256)
k3_head(const float* __restrict__ gamma, const float* __restrict__ beta,
        const float* __restrict__ gw, const float* __restrict__ gb,
        float* __restrict__ out)
{
    __shared__ float swT[18 * 64];       // [k][o]
    __shared__ float sbias[OC];
    __shared__ float sstat[18];
    __shared__ float sgam[9], sbet[9];

    const int tid = threadIdx.x;

    for (int idx = tid; idx < OC * 18; idx += 256) {
        int o = idx / 18, k = idx - o * 18;
        swT[k * 64 + o] = gw[idx];
    }
    if (tid < OC) sbias[tid] = gb[tid];
    if (tid >= 96 && tid < 105) {
        int j = tid - 96;
        int c = j / 3, p = j - c * 3;
        sgam[j] = gamma[p * 3 + c];
        sbet[j] = beta[p * 3 + c];
    }
    if (tid >= 64 && tid < 73) {
        int j = tid - 64;
        double m  = (double)(long long)g_isum[j] * (1.0 / S_SUM) * (1.0 / 8192.0);
        double eq = (double)(long long)g_isq[j]  * (1.0 / S_SQ)  * (1.0 / 8192.0);
        double var = eq - m * m;
        if (var < 0.0) var = 0.0;
        sstat[j] = (float)m;
        sstat[9 + j] = (float)(1.0 / sqrt(var + (double)BN_EPS));
    }
    __syncthreads();

    const int wid = tid >> 5, lane = tid & 31;
    const int gwarp = blockIdx.x * 8 + wid;
    const int nwarp = gridDim.x * 8;
    const float bias0 = sbias[lane], bias1 = sbias[lane + 32];

    for (int pt = gwarp; pt < NPT; pt += nwarp) {
        float f = 0.f;
        if (lane < 9) {
            f = out[OFF_H0 + pt * 9 + lane];
        } else if (lane < 18) {
            int j = lane - 9;
            float x = g_conv[j * NPT + pt];
            f = sgam[j] * (x - sstat[j]) * sstat[9 + j] + sbet[j];
            out[OFF_NF + pt * 9 + j] = f;
        }

        float acc0 = bias0, acc1 = bias1;
#pragma unroll
        for (int k = 0; k < 18; k++) {
            float fv = __shfl_sync(0xffffffffu, f, k);
            acc0 = fmaf(fv, swT[k * 64 + lane], acc0);
            acc1 = fmaf(fv, swT[k * 64 + lane + 32], acc1);
        }
        out[OFF_Y + pt * OC + lane] = acc0;
        out[OFF_Y + pt * OC + lane + 32] = acc1;
    }
}

// ============================================================
extern "C" void kernel_launch(void* const* d_in, const int* in_sizes, int n_in,
                              void* d_out, int out_size)
{
    const float* xc    = (const float*)d_in[0];
    const float* yc    = (const float*)d_in[1];
    const float* xg    = (const float*)d_in[2];
    const float* sigma = (const float*)d_in[3];
    const float* mu    = (const float*)d_in[4];
    const float* eps1  = (const float*)d_in[5];
    const float* bu    = (const float*)d_in[6];
    const float* rw    = (const float*)d_in[7];
    const float* w1    = (const float*)d_in[8];
    const float* b1    = (const float*)d_in[9];
    const float* w2    = (const float*)d_in[10];
    const float* b2    = (const float*)d_in[11];
    const float* w3    = (const float*)d_in[12];
    const float* b3    = (const float*)d_in[13];
    const float* gamma = (const float*)d_in[14];
    const float* beta  = (const float*)d_in[15];
    const float* gw    = (const float*)d_in[16];
    const float* gb    = (const float*)d_in[17];
    float* out = (float*)d_out;

    k0_bucket<<<NB * 3, NC>>>(xc, yc);
    dim3 grid1(NG / 16, NB);
    k1_rbf<<<grid1, 256>>>(xg, sigma, mu, eps1, bu, rw, out);
    k2_conv<<<144, 512>>>(w1, b1, w2, b2, w3, b3);
    k3_head<<<296, 256>>>(gamma, beta, gw, gb, out);
}

// round 16
// speedup vs baseline: 1.0714x; 1.0714x over previous
#include <cuda_runtime.h>
#include <cstdint>

// ---------------- problem constants ----------------
#define NB 4
#define NC 512
#define NG 2048
#define CH 3
#define OC 64
#define NBAS 10
#define NPT 8192
#define NBIN 64
#define EPSV 1e-6f
#define BN_EPS 1e-5f

// output layout (float32, concatenated in return order)
#define OFF_Y   0
#define OFF_NF  524288
#define OFF_FP  598016
#define OFF_NH1 671744
#define OFF_H0  745472

// scratch (device globals)
__device__ float g_pos[9 * NPT];          // SoA [chan][b*NG+g]
__device__ float g_conv[9 * NPT];
__device__ float2 g_sxy[NB * 3 * NC];     // bucketed (x,y) per (b,coord)
__device__ int   g_bstart[NB * 3 * (NBIN + 1)];
__device__ float g_binfo[NB * 3 * 2];     // min, scale per (b,coord)
__device__ unsigned long long g_isum[9];
__device__ unsigned long long g_isq[9];

#define S_SUM 1.7179869184e10   // 2^34
#define S_SQ  2.68435456e8      // 2^28

__device__ __forceinline__ float ex2f(float x) {
    float y;
    asm("ex2.approx.ftz.f32 %0, %1;" : "=f"(y) : "f"(x));
    return y;
}

// ============================================================
// Kernel 0: deterministic 64-bin bucket multisplit per (b,coord).
//           (unchanged -- proven R10/R12)
// ============================================================
__global__ void __launch_bounds__(NC)
k0_bucket(const float* __restrict__ xc, const float* __restrict__ yc)
{
    __shared__ float sx[NC], sy[NC];
    __shared__ int scnt[16 * NBIN];      // [warp][bin]
    __shared__ int stotal[NBIN];
    __shared__ int sbstart[NBIN + 1];
    __shared__ float wmn[16], wmx[16];
    __shared__ float sminv, sscale;

    const int bc = blockIdx.x;           // 0..11
    const int b = bc / 3, c = bc - b * 3;
    const int t = threadIdx.x;
    const int w = t >> 5, lane = t & 31;

    if (bc == 0 && t < 9) { g_isum[t] = 0ull; g_isq[t] = 0ull; }

    float x = xc[(b * NC + t) * 3 + c];
    float y = yc[(b * NC + t) * 3 + c];

    scnt[t] = 0;
    scnt[NC + t] = 0;

    float mn = x, mx = x;
#pragma unroll
    for (int off = 16; off > 0; off >>= 1) {
        mn = fminf(mn, __shfl_xor_sync(0xffffffffu, mn, off));
        mx = fmaxf(mx, __shfl_xor_sync(0xffffffffu, mx, off));
    }
    if (lane == 0) { wmn[w] = mn; wmx[w] = mx; }
    __syncthreads();
    if (t == 0) {
        float m = wmn[0], M = wmx[0];
#pragma unroll
        for (int i = 1; i < 16; i++) { m = fminf(m, wmn[i]); M = fmaxf(M, wmx[i]); }
        sminv = m;
        sscale = (M > m) ? 63.9999f / (M - m) : 0.0f;
    }
    __syncthreads();

    const float mnv = sminv, sc = sscale;
    int bin = (int)((x - mnv) * sc);
    bin = min(max(bin, 0), NBIN - 1);

    unsigned msk = __match_any_sync(0xffffffffu, bin);
    int rank = __popc(msk & ((1u << lane) - 1u));
    if (rank == 0) scnt[w * NBIN + bin] = __popc(msk);
    __syncthreads();

    if (t < NBIN) {
        int run = 0;
#pragma unroll
        for (int w2 = 0; w2 < 16; w2++) {
            int v = scnt[w2 * NBIN + t];
            scnt[w2 * NBIN + t] = run;
            run += v;
        }
        stotal[t] = run;
    }
    __syncthreads();

    for (int off = 1; off < NBIN; off <<= 1) {
        int v = 0;
        if (t < NBIN && t >= off) v = stotal[t - off];
        __syncthreads();
        if (t < NBIN && t >= off) stotal[t] += v;
        __syncthreads();
    }
    if (t < NBIN) sbstart[t + 1] = stotal[t];
    if (t == 0) sbstart[0] = 0;
    __syncthreads();

    int pos = sbstart[bin] + scnt[w * NBIN + bin] + rank;
    sx[pos] = x;
    sy[pos] = y;
    __syncthreads();

    g_sxy[bc * NC + t] = make_float2(sx[t], sy[t]);
    if (t < NBIN + 1) g_bstart[bc * (NBIN + 1) + t] = sbstart[t];
    if (t == 0) { g_binfo[bc * 2] = mnv; g_binfo[bc * 2 + 1] = sc; }
}

// ============================================================
// Kernel 1: windowed RBF sums + fourier prior.
//           R14 structure (1 point/warp, grid 1024) with
//           R = 7.0*sigma_max (annulus weight <= 2.3e-11).
// ============================================================
__global__ void __launch_bounds__(256)
k1_rbf(const float* __restrict__ xg, const float* __restrict__ sigma,
       const float* __restrict__ mu, const float* __restrict__ eps1,
       const float* __restrict__ bu, const float* __restrict__ rw,
       float* __restrict__ out)
{
    __shared__ float2 sxy[3 * NC];
    __shared__ int sbs[3 * (NBIN + 1)];
    __shared__ float sminf[3], sscalef[3];
    __shared__ float ssw[NBAS * 3], ssb[NBAS * 3];
    __shared__ float scoef[3];
    __shared__ float sRmax;
    __shared__ int   sktab[12];          // fourier k-index table [grp*4+i]
    __shared__ float swgt[12];           // fourier weights (0 = dummy pad)
    __shared__ float sred[8][144];       // per-warp reduce scratch [r<8][18]

    const int b = blockIdx.y;
    const int tid = threadIdx.x;

    for (int idx = tid; idx < 3 * NC; idx += 256)
        sxy[idx] = g_sxy[b * 3 * NC + idx];
    for (int idx = tid; idx < 3 * (NBIN + 1); idx += 256)
        sbs[idx] = g_bstart[b * 3 * (NBIN + 1) + idx];
    if (tid < 3) {
        sminf[tid]   = g_binfo[(b * 3 + tid) * 2];
        sscalef[tid] = g_binfo[(b * 3 + tid) * 2 + 1];
    }
    if (tid >= 128 && tid < 128 + NBAS * 3) {
        int q = tid - 128;
        int k = q / 3, p = q - k * 3;
        float w_std = 1.0f / (expf(sigma[p]) + EPSV);
        ssw[q] = expf(mu[p]) + w_std * eps1[(b * NBAS + k) * 3 + p];
        ssb[q] = 6.283185307179586f * bu[(b * NBAS + k) * 3 + p];
    }
    if (tid >= 176 && tid < 179) {
        int p = tid - 176;
        float s = expf(sigma[p]) + EPSV;
        float inv = 1.0f / s;
        scoef[p] = -0.5f * inv * inv * 1.4426950408889634f;
    }
    if (tid == 192) {
        float s0 = expf(sigma[0]) + EPSV;
        float s1 = expf(sigma[1]) + EPSV;
        float s2 = expf(sigma[2]) + EPSV;
        sRmax = 7.0f * fmaxf(s0, fmaxf(s1, s2));
    }
    if (tid >= 200 && tid < 212) {
        int e = tid - 200;
        int grp = e >> 2, i = e & 3;
        int kk; float wv;
        if (grp == 0)      { kk = i;                       wv = rw[i]; }
        else if (grp == 1) { kk = (i < 3) ? 4 + i : 0;     wv = (i < 3) ? rw[4 + i] : 0.f; }
        else               { kk = (i < 3) ? 7 + i : 0;     wv = (i < 3) ? rw[7 + i] : 0.f; }
        sktab[e] = kk;
        swgt[e] = wv;
    }
    __syncthreads();

    const int wid = tid >> 5, lane = tid & 31;
    const int g = blockIdx.x * 8 + wid;
    const float* xgp = &xg[(b * NG + g) * 3];
    const float xg0 = xgp[0], xg1 = xgp[1], xg2 = xgp[2];
    const float c0 = scoef[0], c1 = scoef[1], c2 = scoef[2];
    const float R = sRmax;

    float h0[9], h1[9];

    {
        const float xgv3[3] = { xg0, xg1, xg2 };
#pragma unroll
        for (int c = 0; c < 3; c++) {
            const float xgc = xgv3[c];
            const float2* sp = sxy + c * NC;
            const int* bsc = sbs + c * (NBIN + 1);
            const float mnc = sminf[c], scc = sscalef[c];

            int il = (int)floorf((xgc - R - mnc) * scc);
            int ih = (int)floorf((xgc + R - mnc) * scc);
            il = min(max(il, 0), NBIN - 1);
            ih = min(max(ih, 0), NBIN - 1);
            const int lo = bsc[il], hi = bsc[ih + 1];

            float a0 = 0.f, a1 = 0.f, a2 = 0.f;
            float b0 = 0.f, b1 = 0.f, b2 = 0.f;
            for (int n = lo + lane; n < hi; n += 32) {
                float2 v = sp[n];
                float d = v.x - xgc;
                float s = d * d;
                float e;
                e = ex2f(s * c0); a0 += e; b0 = fmaf(e, v.y, b0);
                e = ex2f(s * c1); a1 += e; b1 = fmaf(e, v.y, b1);
                e = ex2f(s * c2); a2 += e; b2 = fmaf(e, v.y, b2);
            }
            h0[c * 3 + 0] = a0; h1[c * 3 + 0] = b0;
            h0[c * 3 + 1] = a1; h1[c * 3 + 1] = b1;
            h0[c * 3 + 2] = a2; h1[c * 3 + 2] = b2;
        }
    }

    // partial butterfly: offsets 16, 8 -> mod-8 partials
#pragma unroll
    for (int off = 16; off >= 8; off >>= 1) {
#pragma unroll
        for (int j = 0; j < 9; j++) {
            h0[j] += __shfl_xor_sync(0xffffffffu, h0[j], off);
            h1[j] += __shfl_xor_sync(0xffffffffu, h1[j], off);
        }
    }
    if (lane < 8) {
#pragma unroll
        for (int j = 0; j < 9; j++) {
            sred[wid][lane * 18 + j]     = h0[j];
            sred[wid][lane * 18 + 9 + j] = h1[j];
        }
    }
    __syncwarp();
    float hsum = 0.f;
    {
        int le = (lane < 18) ? lane : 0;
#pragma unroll
        for (int r = 0; r < 8; r++)
            hsum += sred[wid][r * 18 + le];
    }
    float h1v = __shfl_sync(0xffffffffu, hsum, lane + 9);   // valid lane<9

    // fourier: 27 lanes, 4 uniform cos each (zero-weight pads)
    float fpart = 0.f;
    {
        int le = (lane < 27) ? lane : 26;
        int grp = le / 9;
        int j = le - grp * 9;
        int c = j / 3, p = j - c * 3;
        float xgc = (c == 0) ? xg0 : ((c == 1) ? xg1 : xg2);
#pragma unroll
        for (int i = 0; i < 4; i++) {
            int e = grp * 4 + i;
            int kk = sktab[e];
            float arg = __fadd_rn(__fmul_rn(ssw[kk * 3 + p], xgc), ssb[kk * 3 + p]);
            fpart = fmaf(swgt[e], cosf(arg), fpart);
        }
    }
    float fpB = __shfl_sync(0xffffffffu, fpart, lane + 9);
    float fpC = __shfl_sync(0xffffffffu, fpart, lane + 18);

    if (lane < 9) {
        float h0v = hsum;
        float nh1 = h1v / (h0v + EPSV);
        float fp = ((fpart + fpB) + fpC) * 0.4472135954999579f;

        int pt = b * NG + g;
        int base = pt * 9 + lane;
        out[OFF_H0 + base] = h0v;
        out[OFF_NH1 + base] = nh1;
        out[OFF_FP + base] = fp;
        g_pos[lane * NPT + pt] = nh1 + fp;
    }
}

// ============================================================
// Kernel 2: depthwise convs + deterministic BN partial sums.
//           Reduction via fp64 warp shuffles (1 syncthreads).
// ============================================================
__global__ void __launch_bounds__(512)
k2_conv(const float* __restrict__ w1, const float* __restrict__ b1,
        const float* __restrict__ w2, const float* __restrict__ b2,
        const float* __restrict__ w3, const float* __restrict__ b3)
{
    __shared__ double swp[16], swq[16];
    const int tid = threadIdx.x;
    const int wid = tid >> 5, lane = tid & 31;
    const int t = blockIdx.x * 512 + tid;
    const int chan = blockIdx.x >> 4;
    const int rem = t - chan * NPT;
    const int g = rem & (NG - 1);
    const int c = chan / 3, p = chan - c * 3;

    const int ksz = (p == 0) ? 3 : ((p == 1) ? 5 : 9);
    const int pad = ksz >> 1;
    const float* w  = (p == 0) ? w1 : ((p == 1) ? w2 : w3);
    const float* bb = (p == 0) ? b1 : ((p == 1) ? b2 : b3);

    float acc = bb[c];
    const float* src = &g_pos[t - g];
    for (int tt = 0; tt < ksz; tt++) {
        int gg = g + tt - pad;
        if (gg >= 0 && gg < NG)
            acc = fmaf(src[gg], w[c * ksz + tt], acc);
    }
    g_conv[t] = acc;

    double v = (double)acc;
    double vq = v * v;
#pragma unroll
    for (int off = 16; off > 0; off >>= 1) {
        v  += __shfl_down_sync(0xffffffffu, v, off);
        vq += __shfl_down_sync(0xffffffffu, vq, off);
    }
    if (lane == 0) { swp[wid] = v; swq[wid] = vq; }
    __syncthreads();
    if (wid == 0) {
        double s = (lane < 16) ? swp[lane] : 0.0;
        double q = (lane < 16) ? swq[lane] : 0.0;
#pragma unroll
        for (int off = 8; off > 0; off >>= 1) {
            s += __shfl_down_sync(0xffffffffu, s, off);
            q += __shfl_down_sync(0xffffffffu, q, off);
        }
        if (lane == 0) {
            long long is = __double2ll_rn(s * S_SUM);
            long long iq = __double2ll_rn(q * S_SQ);
            atomicAdd(&g_isum[chan], (unsigned long long)is);
            atomicAdd(&g_isq[chan],  (unsigned long long)iq);
        }
    }
}

// ============================================================
// Kernel 3: warp-per-point barrier-free head (unchanged R13).
// ============================================================
__global__ void __launch_bounds__(256)
k3_head(const float* __restrict__ gamma, const float* __restrict__ beta,
        const float* __restrict__ gw, const float* __restrict__ gb,
        float* __restrict__ out)
{
    __shared__ float swT[18 * 64];       // [k][o]
    __shared__ float sbias[OC];
    __shared__ float sstat[18];
    __shared__ float sgam[9], sbet[9];

    const int tid = threadIdx.x;

    for (int idx = tid; idx < OC * 18; idx += 256) {
        int o = idx / 18, k = idx - o * 18;
        swT[k * 64 + o] = gw[idx];
    }
    if (tid < OC) sbias[tid] = gb[tid];
    if (tid >= 96 && tid < 105) {
        int j = tid - 96;
        int c = j / 3, p = j - c * 3;
        sgam[j] = gamma[p * 3 + c];
        sbet[j] = beta[p * 3 + c];
    }
    if (tid >= 64 && tid < 73) {
        int j = tid - 64;
        double m  = (double)(long long)g_isum[j] * (1.0 / S_SUM) * (1.0 / 8192.0);
        double eq = (double)(long long)g_isq[j]  * (1.0 / S_SQ)  * (1.0 / 8192.0);
        double var = eq - m * m;
        if (var < 0.0) var = 0.0;
        sstat[j] = (float)m;
        sstat[9 + j] = (float)(1.0 / sqrt(var + (double)BN_EPS));
    }
    __syncthreads();

    const int wid = tid >> 5, lane = tid & 31;
    const int gwarp = blockIdx.x * 8 + wid;
    const int nwarp = gridDim.x * 8;
    const float bias0 = sbias[lane], bias1 = sbias[lane + 32];

    for (int pt = gwarp; pt < NPT; pt += nwarp) {
        float f = 0.f;
        if (lane < 9) {
            f = out[OFF_H0 + pt * 9 + lane];
        } else if (lane < 18) {
            int j = lane - 9;
            float x = g_conv[j * NPT + pt];
            f = sgam[j] * (x - sstat[j]) * sstat[9 + j] + sbet[j];
            out[OFF_NF + pt * 9 + j] = f;
        }

        float acc0 = bias0, acc1 = bias1;
#pragma unroll
        for (int k = 0; k < 18; k++) {
            float fv = __shfl_sync(0xffffffffu, f, k);
            acc0 = fmaf(fv, swT[k * 64 + lane], acc0);
            acc1 = fmaf(fv, swT[k * 64 + lane + 32], acc1);
        }
        out[OFF_Y + pt * OC + lane] = acc0;
        out[OFF_Y + pt * OC + lane + 32] = acc1;
    }
}

// ============================================================
extern "C" void kernel_launch(void* const* d_in, const int* in_sizes, int n_in,
                              void* d_out, int out_size)
{
    const float* xc    = (const float*)d_in[0];
    const float* yc    = (const float*)d_in[1];
    const float* xg    = (const float*)d_in[2];
    const float* sigma = (const float*)d_in[3];
    const float* mu    = (const float*)d_in[4];
    const float* eps1  = (const float*)d_in[5];
    const float* bu    = (const float*)d_in[6];
    const float* rw    = (const float*)d_in[7];
    const float* w1    = (const float*)d_in[8];
    const float* b1    = (const float*)d_in[9];
    const float* w2    = (const float*)d_in[10];
    const float* b2    = (const float*)d_in[11];
    const float* w3    = (const float*)d_in[12];
    const float* b3    = (const float*)d_in[13];
    const float* gamma = (const float*)d_in[14];
    const float* beta  = (const float*)d_in[15];
    const float* gw    = (const float*)d_in[16];
    const float* gb    = (const float*)d_in[17];
    float* out = (float*)d_out;

    k0_bucket<<<NB * 3, NC>>>(xc, yc);
    dim3 grid1(NG / 8, NB);
    k1_rbf<<<grid1, 256>>>(xg, sigma, mu, eps1, bu, rw, out);
    k2_conv<<<144, 512>>>(w1, b1, w2, b2, w3, b3);
    k3_head<<<296, 256>>>(gamma, beta, gw, gb, out);
}